// round 7
// baseline (speedup 1.0000x reference)
#include <cuda_runtime.h>

#define BB 32
#define TT 1024
#define NN 128
#define RBLK 4                      // row-blocks per batch -> 128 CTAs
#define ROWS 32                     // rows per CTA
#define THREADS 256
#define TRR 2                       // rows per thread
#define TC 8                        // cols per thread
#define LANES 16                    // lane-groups per row (128/TC)
#define CHUNK 32
#define NCHUNK (TT / CHUNK)

// pbuf in float2 units: [step][q][lane], q-stride 17 (pad), step-stride 273
#define PB_Q    17
#define PB_STEP 273

// smem layout (floats)
#define SM_XS     0
#define SM_PBUF   (2 * CHUNK * NN)                    // 8192
#define SM_SCOEF  (SM_PBUF + CHUNK * PB_STEP * 2)     // +17472
#define SM_CSCALE (SM_SCOEF + TT + 32)                // pad for over-read
#define SM_CFOLD  (SM_CSCALE + TT)
#define SM_APOW   (SM_CFOLD + NCHUNK)
#define SM_APOWI  (SM_APOW + CHUNK + 1)
#define SM_MBITS  (SM_APOWI + CHUNK + 1)
#define SM_FLOATS (SM_MBITS + NCHUNK)
#define SM_BYTES  (SM_FLOATS * 4)

typedef unsigned long long u64;

// ---------- packed f32x2 helpers ----------
__device__ __forceinline__ u64 pack2(float lo, float hi) {
    u64 r; asm("mov.b64 %0, {%1, %2};" : "=l"(r) : "f"(lo), "f"(hi)); return r;
}
__device__ __forceinline__ void unpack2(u64 v, float& lo, float& hi) {
    asm("mov.b64 {%0, %1}, %2;" : "=f"(lo), "=f"(hi) : "l"(v));
}
__device__ __forceinline__ u64 fma2(u64 a, u64 b, u64 c) {
    u64 d; asm("fma.rn.f32x2 %0, %1, %2, %3;" : "=l"(d) : "l"(a), "l"(b), "l"(c)); return d;
}
__device__ __forceinline__ u64 mul2(u64 a, u64 b) {
    u64 d; asm("mul.rn.f32x2 %0, %1, %2;" : "=l"(d) : "l"(a), "l"(b)); return d;
}
__device__ __forceinline__ u64 add2(u64 a, u64 b) {
    u64 d; asm("add.rn.f32x2 %0, %1, %2;" : "=l"(d) : "l"(a), "l"(b)); return d;
}

// ---------- cp.async ----------
__device__ __forceinline__ void cpasync16(void* s, const void* g) {
    unsigned saddr = (unsigned)__cvta_generic_to_shared(s);
    asm volatile("cp.async.cg.shared.global [%0], [%1], 16;" :: "r"(saddr), "l"(g));
}
// 4096 floats / 256 threads = 16 floats = 4 x 16B per thread
__device__ __forceinline__ void load_chunk(float* dst, const float* src, int tid) {
    #pragma unroll
    for (int i = 0; i < 4; i++) {
        int off = (tid + i * THREADS) * 4;
        cpasync16(dst + off, src + off);
    }
}

__global__ __launch_bounds__(THREADS, 1)
void bdh_scan_kernel(const float* __restrict__ x,
                     const float* __restrict__ w_init,
                     const float* __restrict__ alpha_p,
                     const float* __restrict__ eta_p,
                     const int*   __restrict__ mask,
                     float* __restrict__ w_out,
                     float* __restrict__ y_out)
{
    extern __shared__ float smem[];
    float*    xs     = smem + SM_XS;
    float2*   pbuf   = reinterpret_cast<float2*>(smem + SM_PBUF);
    float*    scoef  = smem + SM_SCOEF;
    float*    cscale = smem + SM_CSCALE;
    float*    cfold  = smem + SM_CFOLD;
    float*    apow   = smem + SM_APOW;
    float*    apowi  = smem + SM_APOWI;
    unsigned* mbits  = (unsigned*)(smem + SM_MBITS);

    const int b    = blockIdx.x;
    const int rb   = blockIdx.y;
    const int tid  = threadIdx.x;
    const int q    = tid >> 4;            // 0..15 row-group (2 rows)
    const int lane = tid & 15;            // 0..15
    const int r0l  = q * TRR;             // local first row
    const int r0   = rb * ROWS + r0l;     // global first row
    const int cseg = lane * TC;

    const float alpha = alpha_p[0];
    const float eta   = eta_p[0];
    const float inva  = 1.0f / alpha;

    const float* xb = x + (size_t)b * TT * NN;
    float* yb = y_out + (size_t)b * TT * NN;

    // prefetch first two x chunks immediately
    load_chunk(xs, xb, tid);
    asm volatile("cp.async.commit_group;");
    load_chunk(xs + CHUNK * NN, xb + CHUNK * NN, tid);
    asm volatile("cp.async.commit_group;");

    // W tile: 2 rows x 8 cols = 8 packed f32x2
    u64 w2[TRR][4];
    {
        const float* wb = w_init + (size_t)b * NN * NN + (size_t)r0 * NN + cseg;
        #pragma unroll
        for (int i = 0; i < TRR; i++) {
            const ulonglong2* ws = reinterpret_cast<const ulonglong2*>(wb + i * NN);
            ulonglong2 v0 = ws[0], v1 = ws[1];
            w2[i][0] = v0.x; w2[i][1] = v0.y; w2[i][2] = v1.x; w2[i][3] = v1.y;
        }
    }

    // ---- setup tables (once) ----
    {
        const int l32 = tid & 31, wi = tid >> 5;
        for (int ckk = wi; ckk < NCHUNK; ckk += 8) {
            int m = mask[(size_t)b * TT + ckk * 32 + l32];
            unsigned bits = __ballot_sync(0xffffffffu, m != 0);
            if (l32 == 0) mbits[ckk] = bits;
        }
    }
    if (tid == 0) {
        float p = 1.0f, pi = 1.0f;
        #pragma unroll
        for (int k = 0; k <= CHUNK; k++) {
            apow[k] = p;  apowi[k] = pi;
            p *= alpha;   pi *= inva;
        }
    }
    __syncthreads();

    // per-step coefficient tables (all chunks)
    #pragma unroll
    for (int k = 0; k < 4; k++) {
        const int e  = tid + k * THREADS;      // 0..1023
        const int ckk = e >> 5, tl = e & 31;
        const unsigned mb = mbits[ckk];
        const int cnt = __popc(mb & ((1u << tl) - 1u));
        cscale[e] = apow[cnt];
        scoef[e]  = ((mb >> tl) & 1u) ? (eta * apowi[cnt + 1]) : 0.0f;
    }
    if (tid < NCHUNK) cfold[tid] = apow[__popc(mbits[tid])];
    if (tid >= THREADS - 32) scoef[TT + (tid & 31)] = 0.0f;   // over-read pad
    __syncthreads();

    for (int ck = 0; ck < NCHUNK; ck++) {
        asm volatile("cp.async.wait_group 1;");
        __syncthreads();

        const float* xch = xs + (ck & 1) * (CHUNK * NN);
        const float* scp = scoef + ck * CHUNK;

        // ---- software-pipelined, branch-free step loop ----
        ulonglong2 va = reinterpret_cast<const ulonglong2*>(xch + cseg)[0];
        ulonglong2 vb = reinterpret_cast<const ulonglong2*>(xch + cseg)[1];
        float2 xr = *reinterpret_cast<const float2*>(xch + rb * ROWS + r0l);
        float  sc = scp[0];

        #pragma unroll 16
        for (int tl = 0; tl < CHUNK; tl++) {
            const u64 xv0 = va.x, xv1 = va.y, xv2 = vb.x, xv3 = vb.y;
            const float2 xrc = xr;
            const float  scc = sc;

            // prefetch next step (tl==31 over-reads adjacent smem; unused/padded)
            const float* xpn = xch + (tl + 1) * NN;
            va = reinterpret_cast<const ulonglong2*>(xpn + cseg)[0];
            vb = reinterpret_cast<const ulonglong2*>(xpn + cseg)[1];
            xr = *reinterpret_cast<const float2*>(xpn + rb * ROWS + r0l);
            sc = scp[tl + 1];

            // 2 dot chains (pre-update W)
            float p0, p1;
            {
                u64 a = mul2(w2[0][0], xv0);
                a = fma2(w2[0][1], xv1, a);
                a = fma2(w2[0][2], xv2, a);
                a = fma2(w2[0][3], xv3, a);
                float lo, hi; unpack2(a, lo, hi);
                p0 = lo + hi;
            }
            {
                u64 a = mul2(w2[1][0], xv0);
                a = fma2(w2[1][1], xv1, a);
                a = fma2(w2[1][2], xv2, a);
                a = fma2(w2[1][3], xv3, a);
                float lo, hi; unpack2(a, lo, hi);
                p1 = lo + hi;
            }
            pbuf[tl * PB_STEP + q * PB_Q + lane] = make_float2(p0, p1);

            // branch-free update (scc == 0 on unmasked steps)
            const float g0f = scc * xrc.x, g1f = scc * xrc.y;
            const u64 g0 = pack2(g0f, g0f);
            const u64 g1 = pack2(g1f, g1f);
            w2[0][0] = fma2(g0, xv0, w2[0][0]);
            w2[0][1] = fma2(g0, xv1, w2[0][1]);
            w2[0][2] = fma2(g0, xv2, w2[0][2]);
            w2[0][3] = fma2(g0, xv3, w2[0][3]);
            w2[1][0] = fma2(g1, xv0, w2[1][0]);
            w2[1][1] = fma2(g1, xv1, w2[1][1]);
            w2[1][2] = fma2(g1, xv2, w2[1][2]);
            w2[1][3] = fma2(g1, xv3, w2[1][3]);
        }

        // unconditional decay fold
        {
            const float cf = cfold[ck];
            const u64 c2 = pack2(cf, cf);
            #pragma unroll
            for (int i = 0; i < TRR; i++)
                #pragma unroll
                for (int k = 0; k < 4; k++) w2[i][k] = mul2(w2[i][k], c2);
        }

        __syncthreads();

        const int nk = ck + 2;
        if (nk < NCHUNK)
            load_chunk(xs + (ck & 1) * (CHUNK * NN), xb + (size_t)nk * CHUNK * NN, tid);
        asm volatile("cp.async.commit_group;");

        // ---- bulk reduction: 512 tasks (step, row-pair), 2 per thread ----
        // 8-byte u64 loads only (16B-alignment-safe at odd float2 strides)
        #pragma unroll
        for (int o = 0; o < 2; o++) {
            const int id = tid + o * THREADS;
            const int s  = id >> 4;           // step in chunk
            const int qq = id & 15;           // row-pair group
            const u64* pp = reinterpret_cast<const u64*>(
                pbuf + s * PB_STEP + qq * PB_Q);
            u64 a0 = add2(pp[0],  pp[1]);
            u64 a1 = add2(pp[2],  pp[3]);
            u64 a2 = add2(pp[4],  pp[5]);
            u64 a3 = add2(pp[6],  pp[7]);
            a0 = add2(a0, add2(pp[8],  pp[9]));
            a1 = add2(a1, add2(pp[10], pp[11]));
            a2 = add2(a2, add2(pp[12], pp[13]));
            a3 = add2(a3, add2(pp[14], pp[15]));
            u64 acc = add2(add2(a0, a1), add2(a2, a3));
            const float scy = cscale[ck * CHUNK + s];
            acc = mul2(acc, pack2(scy, scy));
            *reinterpret_cast<u64*>(
                yb + (size_t)(ck * CHUNK + s) * NN + rb * ROWS + qq * 2) = acc;
        }
        // next top __syncthreads orders pbuf reads before overwrite
    }

    // ---- final W ----
    {
        float* wb = w_out + (size_t)b * NN * NN + (size_t)r0 * NN + cseg;
        #pragma unroll
        for (int i = 0; i < TRR; i++) {
            ulonglong2 v0, v1;
            v0.x = w2[i][0]; v0.y = w2[i][1];
            v1.x = w2[i][2]; v1.y = w2[i][3];
            reinterpret_cast<ulonglong2*>(wb + i * NN)[0] = v0;
            reinterpret_cast<ulonglong2*>(wb + i * NN)[1] = v1;
        }
    }
}

extern "C" void kernel_launch(void* const* d_in, const int* in_sizes, int n_in,
                              void* d_out, int out_size) {
    const float* x      = (const float*)d_in[0];
    const float* w_init = (const float*)d_in[1];
    const float* alpha  = (const float*)d_in[2];
    const float* eta    = (const float*)d_in[3];
    const int*   mask   = (const int*)d_in[4];

    float* w_out = (float*)d_out;
    float* y_out = (float*)d_out + (size_t)BB * NN * NN;

    static bool attr_set = false;
    if (!attr_set) {
        cudaFuncSetAttribute(bdh_scan_kernel,
                             cudaFuncAttributeMaxDynamicSharedMemorySize, SM_BYTES);
        attr_set = true;
    }

    dim3 grid(BB, RBLK);
    bdh_scan_kernel<<<grid, THREADS, SM_BYTES>>>(x, w_init, alpha, eta, mask,
                                                 w_out, y_out);
}